// round 5
// baseline (speedup 1.0000x reference)
#include <cuda_runtime.h>
#include <math.h>

#define BB   128
#define TT   256
#define SS   64
#define IIN  3
#define HH   512
#define KK   10
#define CSL  60
#define OUTD 121
#define G4   2048          // 4*H
#define K1TOT 575          // IN+CSL+H
#define K2TOT 512
#define NSPL 8
#define NBLK 128           // barrier blocks (co-resident, distinct SMs)
#define NWRK 168           // worker blocks (spin on progress, no barrier)
#define GRID (NBLK+NWRK)

// ---------------- scratch (static device allocations; no cudaMalloc) ----------
__device__ float g_h1[BB*HH];
__device__ float g_c1[BB*HH];
__device__ float g_h2[BB*HH];
__device__ float g_c2[BB*HH];
__device__ float g_h1T[HH*BB];          // [h][b]
__device__ float g_h2T[HH*BB];          // [h][b]
__device__ float g_p[BB*3*KK];
__device__ float g_winT[CSL*BB];        // [c][b] current window
__device__ float g_winsT[TT*CSL*BB];    // [t][c][b]
__device__ float g_hxT[(size_t)TT*HH*BB];       // [t][h][b]  layer-1 h outputs
__device__ float g_gp[(size_t)NSPL*BB*G4];      // split-K partials [s][b][j]
__device__ float g_l2in[(size_t)TT*BB*G4];      // layer-2 input gates [t][b][j]
__device__ float g_yT[(size_t)HH*TT*BB];        // [h][t*BB+b]  layer-2 outputs

// ---------------- sync state ---------------------------------------------------
__device__ unsigned g_cnt = 0;
__device__ volatile unsigned g_gen = 0;
__device__ int g_prog1 = -1;            // last timestep whose l2in inputs are ready
__device__ int g_prog2 = -1;            // last timestep whose yT is ready
__device__ unsigned g_tile1 = 0;        // l2in work counter (16*TT tiles)
__device__ unsigned g_tile2 = 0;        // out  work counter (TT tiles)

__device__ __forceinline__ void gbar()
{
    __syncthreads();
    if (threadIdx.x == 0){
        unsigned my = g_gen;
        __threadfence();                       // release (CCTL.IVALL)
        if (atomicAdd(&g_cnt, 1u) == NBLK-1u){
            g_cnt = 0;
            __threadfence();
            g_gen = my + 1u;
        } else {
            while (g_gen == my) __nanosleep(64);
        }
        __threadfence();                       // acquire
    }
    __syncthreads();
}

__device__ __forceinline__ float sigf(float x){ return 1.0f/(1.0f+expf(-x)); }

// 8x4 register-tile FMA micro-step on shared buffers
__device__ __forceinline__ void fma8x4(const float* As, const float* Ws,
                                       int kk, int mi, int nj, float acc[8][4])
{
    float4 a0 = *(const float4*)&As[kk*128 + mi*8];
    float4 a1 = *(const float4*)&As[kk*128 + mi*8 + 4];
    float4 wv = *(const float4*)&Ws[kk*128 + nj*4];
    float av[8] = {a0.x,a0.y,a0.z,a0.w,a1.x,a1.y,a1.z,a1.w};
    #pragma unroll
    for (int i=0;i<8;i++){
        acc[i][0] += av[i]*wv.x;
        acc[i][1] += av[i]*wv.y;
        acc[i][2] += av[i]*wv.z;
        acc[i][3] += av[i]*wv.w;
    }
}

// ---------------- init ---------------------------------------------------------
__global__ void k_init(const float* __restrict__ h1h, const float* __restrict__ h1c,
                       const float* __restrict__ h2h, const float* __restrict__ h2c)
{
    int i = blockIdx.x*blockDim.x + threadIdx.x;
    if (i == 0){ g_cnt=0; g_prog1=-1; g_prog2=-1; g_tile1=0; g_tile2=0; }
    if (i < BB*HH){
        int b = i/HH, h = i%HH;
        float a=h1h[i], c=h1c[i], d=h2h[i], e=h2c[i];
        g_h1[i]=a; g_c1[i]=c; g_h2[i]=d; g_c2[i]=e;
        g_h1T[h*BB+b]=a; g_h2T[h*BB+b]=d;
    }
    if (i < BB*3*KK) g_p[i] = 0.f;
}

// ================= persistent layer-1 + overlapped l2in =======================
// blocks < NBLK : barrier blocks — attention + cell + recurrent GEMM
// blocks >= NBLK: workers — l2in(t) tiles, gated on g_prog1
__global__ void __launch_bounds__(512,2)
k_rec1(const float* __restrict__ x,    const float* __restrict__ Wihc,
       const float* __restrict__ Whhc, const float* __restrict__ bc,
       const float* __restrict__ W1,   const float* __restrict__ b1,
       const float* __restrict__ sent,
       const float* __restrict__ Wihl, const float* __restrict__ bl)
{
    __shared__ float Wp[72*128];       // barrier: persistent W tile; worker: Ws staging
    __shared__ float As[8*128];
    __shared__ float sh[HH];
    __shared__ float sp[3*KK];
    __shared__ float sphi[SS];
    __shared__ unsigned s_tile;

    const int tid = threadIdx.x;
    const int blk = blockIdx.x;
    const int mi = tid & 15, nj = tid >> 4;

    if (blk >= NBLK){
        // ---------------- l2in worker ----------------------------------------
        float* Ws = Wp;
        while (true){
            __syncthreads();
            if (tid == 0) s_tile = atomicAdd(&g_tile1, 1u);
            __syncthreads();
            unsigned tile = s_tile;
            if (tile >= 16u*TT) return;
            int t  = tile >> 4;
            int j0 = (tile & 15) * 128;
            if (tid == 0){
                while (((volatile int*)&g_prog1)[0] < t) __nanosleep(256);
                __threadfence();
            }
            __syncthreads();

            float acc[8][4];
            #pragma unroll
            for (int i=0;i<8;i++){ acc[i][0]=acc[i][1]=acc[i][2]=acc[i][3]=0.f; }

            for (int kt = 0; kt < K1TOT; kt += 8){
                __syncthreads();
                #pragma unroll
                for (int r=0;r<2;r++){
                    int ii = tid + 512*r;
                    int kk = ii >> 7, m = ii & 127;
                    int kg = kt + kk;
                    float v = 0.f;
                    if (kg < K1TOT){
                        if      (kg < IIN) v = x[((size_t)m*TT + t)*IIN + kg];
                        else if (kg < 63)  v = g_winsT[((size_t)t*CSL + (kg-IIN))*BB + m];
                        else               v = g_hxT[((size_t)t*HH + (kg-63))*BB + m];
                    }
                    As[kk*128+m] = v;
                }
                #pragma unroll
                for (int r=0;r<2;r++){
                    int ii = tid + 512*r;
                    int kk = ii & 7, jl = ii >> 3;
                    int kg = kt + kk;
                    Ws[kk*128+jl] = (kg < K1TOT) ? Wihl[(size_t)(j0+jl)*K1TOT + kg] : 0.f;
                }
                __syncthreads();
                #pragma unroll
                for (int kk=0;kk<8;kk++) fma8x4(As, Ws, kk, mi, nj, acc);
            }
            float4 bb4 = *(const float4*)&bl[j0 + nj*4];
            #pragma unroll
            for (int i=0;i<8;i++){
                int m = mi*8+i;
                float4 o = make_float4(acc[i][0]+bb4.x, acc[i][1]+bb4.y,
                                       acc[i][2]+bb4.z, acc[i][3]+bb4.w);
                *(float4*)&g_l2in[((size_t)t*BB + m)*G4 + j0 + nj*4] = o;
            }
        }
    }

    // ---------------- barrier block: recurrence -------------------------------
    const int b   = blk;
    const int j0  = (blk & 15) * 128;
    const int spl = blk >> 4;
    const int k0  = spl * 72;
    const int kend = min(K1TOT, k0 + 72);

    for (int i = tid; i < 72*128; i += 512){
        int kk = i >> 7, jl = i & 127;
        int kg = k0 + kk, j = j0 + jl;
        float v = 0.f;
        if (kg < kend)
            v = (kg < 63) ? Wihc[(size_t)j*63 + kg] : Whhc[(size_t)j*512 + (kg-63)];
        Wp[i] = v;
    }

    for (int t = 0; t < TT; t++){
        // -------- phase A: cell(t-1) + attention(t), block handles batch b ----
        {
            int h = tid;
            if (t > 0){
                float gi=bc[h], gf=bc[HH+h], gg=bc[2*HH+h], go=bc[3*HH+h];
                #pragma unroll
                for (int s=0;s<NSPL;s++){
                    const float* gp = g_gp + (size_t)s*BB*G4 + (size_t)b*G4;
                    gi += gp[h]; gf += gp[HH+h]; gg += gp[2*HH+h]; go += gp[3*HH+h];
                }
                float c  = g_c1[b*HH+h];
                float cn = sigf(gf)*c + sigf(gi)*tanhf(gg);
                float hn = sigf(go)*tanhf(cn);
                g_c1[b*HH+h]=cn;
                g_h1T[h*BB+b]=hn;
                g_hxT[((size_t)(t-1)*HH + h)*BB + b] = hn;
                sh[h]=hn;
            } else {
                sh[h] = g_h1[b*HH+h];
            }
        }
        __syncthreads();

        // attention
        {
            int w = tid>>5, lane = tid&31;
            for (int j = w; j < 3*KK; j += 16){
                float s = 0.f;
                for (int k = lane; k < HH; k += 32) s += sh[k]*W1[j*HH+k];
                #pragma unroll
                for (int o=16;o;o>>=1) s += __shfl_down_sync(0xffffffffu, s, o);
                if (lane == 0){
                    float v = expf(s + b1[j]);
                    if (j >= 2*KK) v -= g_p[b*3*KK + j];
                    g_p[b*3*KK + j] = v;
                    sp[j] = v;
                }
            }
            __syncthreads();
            if (tid < SS){
                float u = (float)(tid+1);
                float acc = 0.f;
                #pragma unroll
                for (int k=0;k<KK;k++){
                    float d = sp[2*KK+k] - u;
                    acc += sp[k]*expf(-sp[KK+k]*d*d);
                }
                sphi[tid] = acc;
            }
            __syncthreads();
            if (tid < CSL){
                float acc = 0.f;
                #pragma unroll 8
                for (int s=0;s<SS;s++) acc += sphi[s]*sent[((size_t)b*SS+s)*CSL + tid];
                g_winT[tid*BB + b] = acc;
                g_winsT[((size_t)t*CSL + tid)*BB + b] = acc;
            }
        }
        gbar();
        if (blk == 0 && tid == 0 && t > 0) ((volatile int*)&g_prog1)[0] = t-1;

        // -------- phase B: recurrent GEMM, SMEM-resident weights --------------
        {
            float acc[8][4];
            #pragma unroll
            for (int i=0;i<8;i++){ acc[i][0]=acc[i][1]=acc[i][2]=acc[i][3]=0.f; }

            for (int kt = 0; kt < 72; kt += 8){
                __syncthreads();
                #pragma unroll
                for (int r=0;r<2;r++){
                    int ii = tid + 512*r;
                    int kk = ii >> 7, m = ii & 127;
                    int kg = k0 + kt + kk;
                    float v = 0.f;
                    if (kg < kend){
                        if      (kg < IIN) v = x[((size_t)m*TT + t)*IIN + kg];
                        else if (kg < 63)  v = g_winT[(kg-IIN)*BB + m];
                        else               v = g_h1T[(kg-63)*BB + m];
                    }
                    As[kk*128+m] = v;
                }
                __syncthreads();
                #pragma unroll
                for (int kk=0;kk<8;kk++) fma8x4(As, &Wp[kt*128], kk, mi, nj, acc);
            }
            float* outp = g_gp + (size_t)spl*BB*G4;
            #pragma unroll
            for (int i=0;i<8;i++){
                int m = mi*8+i;
                *(float4*)(outp + (size_t)m*G4 + j0 + nj*4) =
                    make_float4(acc[i][0],acc[i][1],acc[i][2],acc[i][3]);
            }
        }
        gbar();
    }

    // final cell -> final h1/c1 + hxT[TT-1]
    {
        int h = tid;
        float gi=bc[h], gf=bc[HH+h], gg=bc[2*HH+h], go=bc[3*HH+h];
        #pragma unroll
        for (int s=0;s<NSPL;s++){
            const float* gp = g_gp + (size_t)s*BB*G4 + (size_t)b*G4;
            gi += gp[h]; gf += gp[HH+h]; gg += gp[2*HH+h]; go += gp[3*HH+h];
        }
        float c  = g_c1[b*HH+h];
        float cn = sigf(gf)*c + sigf(gi)*tanhf(gg);
        float hn = sigf(go)*tanhf(cn);
        g_c1[b*HH+h]=cn; g_h1[b*HH+h]=hn;
        g_hxT[((size_t)(TT-1)*HH + h)*BB + b] = hn;
    }
    gbar();
    if (blk == 0 && tid == 0) ((volatile int*)&g_prog1)[0] = TT-1;
}

// ================= persistent layer-2 + overlapped output projection ==========
// blocks < NBLK : barrier blocks — recurrent GEMM + cell2
// blocks >= NBLK: workers — out tile for timestep t, gated on g_prog2
__global__ void __launch_bounds__(512,2)
k_rec2(const float* __restrict__ Whhl,
       const float* __restrict__ W2, const float* __restrict__ b2,
       float* __restrict__ out)
{
    __shared__ float Wp[64*128];   // barrier: persistent W tile; worker: Ws staging
    __shared__ float As[8*128];
    __shared__ unsigned s_tile;

    const int tid = threadIdx.x;
    const int blk = blockIdx.x;
    const int mi = tid & 15, nj = tid >> 4;

    if (blk >= NBLK){
        // ---------------- output-projection worker ----------------------------
        float* Ws = Wp;
        while (true){
            __syncthreads();
            if (tid == 0) s_tile = atomicAdd(&g_tile2, 1u);
            __syncthreads();
            unsigned tile = s_tile;
            if (tile >= TT) return;
            int t  = (int)tile;
            int m0 = t * 128;
            if (tid == 0){
                while (((volatile int*)&g_prog2)[0] < t) __nanosleep(256);
                __threadfence();
            }
            __syncthreads();

            float acc[8][4];
            #pragma unroll
            for (int i=0;i<8;i++){ acc[i][0]=acc[i][1]=acc[i][2]=acc[i][3]=0.f; }

            for (int kt = 0; kt < K2TOT; kt += 8){
                __syncthreads();
                #pragma unroll
                for (int r=0;r<2;r++){
                    int ii = tid + 512*r;
                    int kk = ii >> 7, m = ii & 127;
                    As[kk*128+m] = g_yT[(size_t)(kt+kk)*(TT*BB) + m0 + m];
                }
                #pragma unroll
                for (int r=0;r<2;r++){
                    int ii = tid + 512*r;
                    int kk = ii & 7, jl = ii >> 3;
                    Ws[kk*128+jl] = (jl < OUTD) ? W2[(size_t)jl*K2TOT + kt + kk] : 0.f;
                }
                __syncthreads();
                #pragma unroll
                for (int kk=0;kk<8;kk++) fma8x4(As, Ws, kk, mi, nj, acc);
            }
            #pragma unroll
            for (int i=0;i<8;i++){
                int bb = mi*8+i;                      // batch index within tile
                size_t row = (size_t)(bb*TT + t)*OUTD;
                #pragma unroll
                for (int j=0;j<4;j++){
                    int jg = nj*4 + j;
                    if (jg < OUTD) out[row + jg] = acc[i][j] + b2[jg];
                }
            }
        }
    }

    // ---------------- barrier block: layer-2 recurrence -----------------------
    const int b   = blk;
    const int j0  = (blk & 15) * 128;
    const int spl = blk >> 4;
    const int k0  = spl * 64;

    for (int i = tid; i < 64*128; i += 512){
        int kk = i >> 7, jl = i & 127;
        Wp[i] = Whhl[(size_t)(j0+jl)*K2TOT + k0 + kk];
    }

    for (int t = 0; t < TT; t++){
        // -------- GEMM: partial = h2 @ W_hh_l^T ------------------------------
        {
            float acc[8][4];
            #pragma unroll
            for (int i=0;i<8;i++){ acc[i][0]=acc[i][1]=acc[i][2]=acc[i][3]=0.f; }

            for (int kt = 0; kt < 64; kt += 8){
                __syncthreads();
                #pragma unroll
                for (int r=0;r<2;r++){
                    int ii = tid + 512*r;
                    int kk = ii >> 7, m = ii & 127;
                    As[kk*128+m] = g_h2T[(k0 + kt + kk)*BB + m];
                }
                __syncthreads();
                #pragma unroll
                for (int kk=0;kk<8;kk++) fma8x4(As, &Wp[kt*128], kk, mi, nj, acc);
            }
            float* outp = g_gp + (size_t)spl*BB*G4;
            #pragma unroll
            for (int i=0;i<8;i++){
                int m = mi*8+i;
                *(float4*)(outp + (size_t)m*G4 + j0 + nj*4) =
                    make_float4(acc[i][0],acc[i][1],acc[i][2],acc[i][3]);
            }
        }
        gbar();

        // -------- cell2(t): block handles batch b, h = tid --------------------
        {
            const float* li = g_l2in + ((size_t)t*BB + b)*G4;
            int h = tid;
            float gi = li[h], gf = li[HH+h], gg = li[2*HH+h], go = li[3*HH+h];
            #pragma unroll
            for (int s=0;s<NSPL;s++){
                const float* gp = g_gp + (size_t)s*BB*G4 + (size_t)b*G4;
                gi += gp[h]; gf += gp[HH+h]; gg += gp[2*HH+h]; go += gp[3*HH+h];
            }
            float c  = g_c2[b*HH+h];
            float cn = sigf(gf)*c + sigf(gi)*tanhf(gg);
            float hn = sigf(go)*tanhf(cn);
            g_c2[b*HH+h]=cn;
            g_h2T[h*BB+b]=hn;
            g_yT[(size_t)h*(TT*BB) + t*BB + b] = hn;
            if (t == TT-1) g_h2[b*HH+h] = hn;
        }
        gbar();
        if (blk == 0 && tid == 0) ((volatile int*)&g_prog2)[0] = t;
    }
}

// ---------------- final states appended after out -----------------------------
__global__ void k_states(float* __restrict__ out, int out_size)
{
    const int base = BB*TT*OUTD;               // 3,964,928
    if (base + 4*BB*HH > out_size) return;
    int i = blockIdx.x*256 + threadIdx.x;
    if (i < BB*HH){
        out[base            + i] = g_h1[i];
        out[base +   BB*HH  + i] = g_c1[i];
        out[base + 2*BB*HH  + i] = g_h2[i];
        out[base + 3*BB*HH  + i] = g_c2[i];
    }
}

// ---------------- launch -------------------------------------------------------
extern "C" void kernel_launch(void* const* d_in, const int* in_sizes, int n_in,
                              void* d_out, int out_size)
{
    const float* x    = (const float*)d_in[0];
    const float* sent = (const float*)d_in[1];
    const float* h1h  = (const float*)d_in[2];
    const float* h1c  = (const float*)d_in[3];
    const float* h2h  = (const float*)d_in[4];
    const float* h2c  = (const float*)d_in[5];
    const float* Wihc = (const float*)d_in[6];
    const float* Whhc = (const float*)d_in[7];
    const float* bc   = (const float*)d_in[8];
    const float* Wihl = (const float*)d_in[9];
    const float* Whhl = (const float*)d_in[10];
    const float* bl   = (const float*)d_in[11];
    const float* W1   = (const float*)d_in[12];
    const float* b1   = (const float*)d_in[13];
    const float* W2   = (const float*)d_in[14];
    const float* b2   = (const float*)d_in[15];
    float* out = (float*)d_out;

    k_init<<<256,256>>>(h1h,h1c,h2h,h2c);

    // layer 1 recurrence + overlapped layer-2 input GEMM (1 launch)
    k_rec1<<<GRID,512>>>(x, Wihc, Whhc, bc, W1, b1, sent, Wihl, bl);

    // layer 2 recurrence + overlapped output projection (1 launch)
    k_rec2<<<GRID,512>>>(Whhl, W2, b2, out);

    // final states
    k_states<<<(BB*HH+255)/256,256>>>(out, out_size);
}

// round 6
// speedup vs baseline: 1.2107x; 1.2107x over previous
#include <cuda_runtime.h>
#include <math.h>

#define BB   128
#define TT   256
#define SS   64
#define IIN  3
#define HH   512
#define KK   10
#define CSL  60
#define OUTD 121
#define G4   2048
#define K1TOT 575
#define K2TOT 512
#define NBLK 128

// ---------------- scratch ------------------------------------------------------
__device__ float g_h1T[2][HH*BB + 64];          // [parity][h][b]
__device__ float g_h2T[2][HH*BB + 64];
__device__ float g_winT[CSL*BB];                // [c][b]
__device__ float g_winsT[TT*CSL*BB];            // [t][c][b]
__device__ float g_hxT[(size_t)TT*HH*BB];       // [t][h][b]
__device__ float g_l2inT[(size_t)TT*G4*BB];     // [t][j][b]
__device__ float g_yT[(size_t)HH*TT*BB];        // [h][t*BB+b]
__device__ float g_h1f[BB*HH], g_c1f[BB*HH], g_h2f[BB*HH], g_c2f[BB*HH];

// ---------------- grid barrier -------------------------------------------------
__device__ unsigned g_cnt = 0;
__device__ volatile unsigned g_gen = 0;

__device__ __forceinline__ void gbar()
{
    __syncthreads();
    if (threadIdx.x == 0){
        unsigned my = g_gen;
        __threadfence();
        if (atomicAdd(&g_cnt, 1u) == NBLK-1u){
            g_cnt = 0;
            __threadfence();
            g_gen = my + 1u;
        } else {
            while (g_gen == my) __nanosleep(64);
        }
        __threadfence();
    }
    __syncthreads();
}

__device__ __forceinline__ float sigf(float x){ return 1.0f/(1.0f+expf(-x)); }

// ---------------- cp.async helpers --------------------------------------------
__device__ __forceinline__ void cpa4(void* dst, const void* src){
    unsigned d = (unsigned)__cvta_generic_to_shared(dst);
    asm volatile("cp.async.ca.shared.global [%0], [%1], 4;" :: "r"(d), "l"(src));
}
__device__ __forceinline__ void cpa16(void* dst, const void* src){
    unsigned d = (unsigned)__cvta_generic_to_shared(dst);
    asm volatile("cp.async.ca.shared.global [%0], [%1], 16;" :: "r"(d), "l"(src));
}
__device__ __forceinline__ void cpcommit(){ asm volatile("cp.async.commit_group;"); }
__device__ __forceinline__ void cpwait0(){ asm volatile("cp.async.wait_group 0;"); }
__device__ __forceinline__ void cpwait1(){ asm volatile("cp.async.wait_group 1;"); }

// ---------------- init ---------------------------------------------------------
__global__ void k_init(const float* __restrict__ h1h, const float* __restrict__ h2h)
{
    int i = blockIdx.x*blockDim.x + threadIdx.x;
    if (i < BB*HH){
        int b = i/HH, h = i%HH;
        g_h1T[0][h*BB+b] = h1h[i];
        g_h2T[0][h*BB+b] = h2h[i];
    }
}

// ================= persistent layer-1 =========================================
// 128 blocks = 64 h-tiles(8h x 4gates) x 2 b-tiles(64b). 512 thr = 8h x 64b.
// Gates + cell state in registers; W SMEM-resident; A cp.async pipelined.
__global__ void __launch_bounds__(512,1)
k_rec1(const float* __restrict__ x,    const float* __restrict__ Wihc,
       const float* __restrict__ Whhc, const float* __restrict__ bc,
       const float* __restrict__ W1,   const float* __restrict__ b1,
       const float* __restrict__ sent, const float* __restrict__ h1c_in)
{
    extern __shared__ float sm[];
    float* Ws    = sm;                    // 576*8*4 = 18432 floats
    float* As    = Ws + 576*8*4;          // 2*4096
    float* sentS = As + 8192;             // 3840
    float* sh    = sentS + 3840;          // 512
    float* sp    = sh + 512;              // 32
    float* sphi  = sp + 32;               // 64

    const int tid = threadIdx.x;
    const int blk = blockIdx.x;
    const int ht = blk >> 1, bt = blk & 1;
    const int h0 = ht*8;
    const int hl = tid >> 6, bl = tid & 63;
    const int hg = h0 + hl;
    const int bG = bt*64 + bl;
    const int b  = blk;                    // attention batch for this block

    // preload gate-interleaved weights: Ws[(k*8+h)*4+g] = W[g*512+h0+h][k]
    for (int idx = tid; idx < 576*8*4; idx += 512){
        int g = idx & 3, h = (idx>>2)&7, k = idx>>5;
        float v = 0.f;
        if (k < K1TOT){
            int j = g*512 + h0 + h;
            v = (k < 63) ? Wihc[(size_t)j*63 + k] : Whhc[(size_t)j*512 + (k-63)];
        }
        Ws[idx] = v;
    }
    for (int idx = tid; idx < SS*CSL; idx += 512)
        sentS[idx] = sent[(size_t)b*SS*CSL + idx];
    if (tid < 32) sp[tid] = 0.f;           // attention ip carry

    float c1r = h1c_in[(size_t)bG*HH + hg];
    const float bi = bc[hg], bf = bc[512+hg], bg2 = bc[1024+hg], bo = bc[1536+hg];
    __syncthreads();

    const float4* Wsv = (const float4*)Ws;

    for (int t = 0; t < TT; t++){
        const float* h1cur = g_h1T[t&1];

        // ---------------- phase A: attention for batch b ----------------------
        sh[tid] = h1cur[tid*BB + b];
        __syncthreads();
        {
            int w = tid>>5, lane = tid&31;
            for (int j = w; j < 30; j += 16){
                float s = 0.f;
                #pragma unroll 8
                for (int k = lane; k < 512; k += 32) s += sh[k]*W1[j*512+k];
                #pragma unroll
                for (int o=16;o;o>>=1) s += __shfl_down_sync(0xffffffffu, s, o);
                if (lane == 0){
                    float v = expf(s + b1[j]);
                    if (j >= 20) v -= sp[j];
                    sp[j] = v;
                }
            }
        }
        __syncthreads();
        if (tid < SS){
            float u = (float)(tid+1), acc = 0.f;
            #pragma unroll
            for (int k=0;k<KK;k++){
                float d = sp[20+k] - u;
                acc += sp[k]*expf(-sp[10+k]*d*d);
            }
            sphi[tid] = acc;
        }
        __syncthreads();
        if (tid < CSL){
            float acc = 0.f;
            #pragma unroll 8
            for (int s=0;s<SS;s++) acc += sphi[s]*sentS[s*CSL + tid];
            g_winT[tid*BB + b] = acc;
            g_winsT[((size_t)t*CSL + tid)*BB + b] = acc;
        }
        gbar();

        // ---------------- phase B: full-K GEMM + in-register cell -------------
        float gi = bi, gf = bf, gg = bg2, go = bo;

        // stage chunk0: k 0..62 (x | win), element-wise cp.async
        for (int idx = tid; idx < 63*64; idx += 512){
            int kk = idx >> 6, bb = bt*64 + (idx & 63);
            const float* src = (kk < 3) ? &x[((size_t)bb*TT + t)*IIN + kk]
                                        : &g_winT[(kk-3)*BB + bb];
            cpa4(&As[idx], src);
        }
        cpcommit();
        // stage chunk1: h 0..63, float4 rows
        for (int q = tid; q < 1024; q += 512){
            int kk = q >> 4, r = q & 15;
            cpa16(&As[4096 + kk*64 + r*4], &h1cur[kk*BB + bt*64 + r*4]);
        }
        cpcommit();

        for (int c = 0; c <= 8; c++){
            if (c == 8) cpwait0(); else cpwait1();
            __syncthreads();
            const float* Ab = As + (c&1)*4096;
            const int klen = c ? 64 : 63;
            const int kof  = c ? 63 + (c-1)*64 : 0;
            #pragma unroll 4
            for (int kk = 0; kk < klen; kk++){
                float  a = Ab[kk*64 + bl];
                float4 w = Wsv[(kof+kk)*8 + hl];
                gi += a*w.x; gf += a*w.y; gg += a*w.z; go += a*w.w;
            }
            __syncthreads();
            if (c+2 <= 8){
                int cc = c+2;
                float* dst = As + (c&1)*4096;
                for (int q = tid; q < 1024; q += 512){
                    int kk = q >> 4, r = q & 15;
                    cpa16(&dst[kk*64 + r*4], &h1cur[((cc-1)*64 + kk)*BB + bt*64 + r*4]);
                }
                cpcommit();
            }
        }

        float cn = sigf(gf)*c1r + sigf(gi)*tanhf(gg);
        float hn = sigf(go)*tanhf(cn);
        c1r = cn;
        g_h1T[(t+1)&1][hg*BB + bG] = hn;
        g_hxT[((size_t)t*HH + hg)*BB + bG] = hn;
        if (t == TT-1){
            g_h1f[(size_t)bG*HH + hg] = hn;
            g_c1f[(size_t)bG*HH + hg] = cn;
        }
        gbar();
    }
}

// ---------------- layer-2 input gates, all t (parallel GEMM) -------------------
// writes TRANSPOSED l2inT[t][j][b]
__global__ void __launch_bounds__(256) k_l2in(const float* __restrict__ x,
        const float* __restrict__ Wih, const float* __restrict__ bl)
{
    __shared__ float As[8][128];
    __shared__ float Ws[8][132];
    int j0 = blockIdx.x*128;
    int t  = blockIdx.y;
    int tid = threadIdx.x;
    int mi = tid & 15, ni = tid >> 4;

    float acc[8][8];
    #pragma unroll
    for (int i=0;i<8;i++)
        #pragma unroll
        for (int j=0;j<8;j++) acc[i][j] = 0.f;

    for (int kt = 0; kt < K1TOT; kt += 8){
        __syncthreads();
        #pragma unroll
        for (int r=0;r<4;r++){
            int ii = tid + 256*r;
            int kk = ii >> 7, m = ii & 127;
            int kg = kt + kk;
            float v = 0.f;
            if (kg < K1TOT){
                if      (kg < IIN) v = x[((size_t)m*TT + t)*IIN + kg];
                else if (kg < 63)  v = g_winsT[((size_t)t*CSL + (kg-IIN))*BB + m];
                else               v = g_hxT[((size_t)t*HH + (kg-63))*BB + m];
            }
            As[kk][m] = v;
        }
        #pragma unroll
        for (int r=0;r<4;r++){
            int ii = tid + 256*r;
            int jl = ii >> 3, kk = ii & 7;
            int kg = kt + kk;
            Ws[kk][jl] = (kg < K1TOT) ? Wih[(size_t)(j0+jl)*K1TOT + kg] : 0.f;
        }
        __syncthreads();
        #pragma unroll
        for (int kk=0;kk<8;kk++){
            float a[8], wv[8];
            #pragma unroll
            for (int i=0;i<8;i++) a[i]  = As[kk][mi*8+i];
            #pragma unroll
            for (int j=0;j<8;j++) wv[j] = Ws[kk][ni*8+j];
            #pragma unroll
            for (int i=0;i<8;i++)
                #pragma unroll
                for (int j=0;j<8;j++) acc[i][j] += a[i]*wv[j];
        }
    }
    // transposed epilogue: l2inT[t][jg][b], b = mi*8..mi*8+7 contiguous
    #pragma unroll
    for (int jj=0;jj<8;jj++){
        int jg = j0 + ni*8 + jj;
        float bv = bl[jg];
        float* p = &g_l2inT[((size_t)t*G4 + jg)*BB + mi*8];
        *(float4*)(p)   = make_float4(acc[0][jj]+bv, acc[1][jj]+bv, acc[2][jj]+bv, acc[3][jj]+bv);
        *(float4*)(p+4) = make_float4(acc[4][jj]+bv, acc[5][jj]+bv, acc[6][jj]+bv, acc[7][jj]+bv);
    }
}

// ================= persistent layer-2 =========================================
// 1 grid barrier per step; gates + c2 in registers; W SMEM-resident.
__global__ void __launch_bounds__(512,1)
k_rec2(const float* __restrict__ Whhl, const float* __restrict__ h2c_in)
{
    extern __shared__ float sm[];
    float* Ws = sm;                 // 512*8*4 = 16384 floats
    float* As = Ws + 16384;         // 2*4096

    const int tid = threadIdx.x;
    const int blk = blockIdx.x;
    const int ht = blk >> 1, bt = blk & 1;
    const int h0 = ht*8;
    const int hl = tid >> 6, bl = tid & 63;
    const int hg = h0 + hl;
    const int bG = bt*64 + bl;

    for (int idx = tid; idx < 512*8*4; idx += 512){
        int g = idx & 3, h = (idx>>2)&7, k = idx>>5;
        Ws[idx] = Whhl[(size_t)(g*512 + h0 + h)*K2TOT + k];
    }
    float c2r = h2c_in[(size_t)bG*HH + hg];
    __syncthreads();

    const float4* Wsv = (const float4*)Ws;

    for (int t = 0; t < TT; t++){
        const float* h2cur = g_h2T[t&1];

        // gate init from l2inT (coalesced by b)
        const float* li = &g_l2inT[(size_t)t*G4*BB];
        float gi = li[(size_t)(hg       )*BB + bG];
        float gf = li[(size_t)(hg +  512)*BB + bG];
        float gg = li[(size_t)(hg + 1024)*BB + bG];
        float go = li[(size_t)(hg + 1536)*BB + bG];

        // stage chunks 0,1
        for (int q = tid; q < 1024; q += 512){
            int kk = q >> 4, r = q & 15;
            cpa16(&As[kk*64 + r*4], &h2cur[kk*BB + bt*64 + r*4]);
        }
        cpcommit();
        for (int q = tid; q < 1024; q += 512){
            int kk = q >> 4, r = q & 15;
            cpa16(&As[4096 + kk*64 + r*4], &h2cur[(64+kk)*BB + bt*64 + r*4]);
        }
        cpcommit();

        for (int c = 0; c <= 7; c++){
            if (c == 7) cpwait0(); else cpwait1();
            __syncthreads();
            const float* Ab = As + (c&1)*4096;
            const int kof = c*64;
            #pragma unroll 4
            for (int kk = 0; kk < 64; kk++){
                float  a = Ab[kk*64 + bl];
                float4 w = Wsv[(kof+kk)*8 + hl];
                gi += a*w.x; gf += a*w.y; gg += a*w.z; go += a*w.w;
            }
            __syncthreads();
            if (c+2 <= 7){
                int cc = c+2;
                float* dst = As + (c&1)*4096;
                for (int q = tid; q < 1024; q += 512){
                    int kk = q >> 4, r = q & 15;
                    cpa16(&dst[kk*64 + r*4], &h2cur[(cc*64 + kk)*BB + bt*64 + r*4]);
                }
                cpcommit();
            }
        }

        float cn = sigf(gf)*c2r + sigf(gi)*tanhf(gg);
        float hn = sigf(go)*tanhf(cn);
        c2r = cn;
        g_h2T[(t+1)&1][hg*BB + bG] = hn;
        g_yT[(size_t)hg*(TT*BB) + t*BB + bG] = hn;
        if (t == TT-1){
            g_h2f[(size_t)bG*HH + hg] = hn;
            g_c2f[(size_t)bG*HH + hg] = cn;
        }
        gbar();
    }
}

// ---------------- output projection -------------------------------------------
__global__ void __launch_bounds__(256) k_out(const float* __restrict__ W2,
        const float* __restrict__ b2, float* __restrict__ out)
{
    __shared__ float As[8][128];
    __shared__ float Ws[8][132];
    int m0 = blockIdx.x*128;
    int tid = threadIdx.x;
    int mi = tid & 15, ni = tid >> 4;

    float acc[8][8];
    #pragma unroll
    for (int i=0;i<8;i++)
        #pragma unroll
        for (int j=0;j<8;j++) acc[i][j] = 0.f;

    for (int kt = 0; kt < K2TOT; kt += 8){
        __syncthreads();
        #pragma unroll
        for (int r=0;r<4;r++){
            int ii = tid + 256*r;
            int kk = ii >> 7, m = ii & 127;
            As[kk][m] = g_yT[(size_t)(kt+kk)*(TT*BB) + m0 + m];
        }
        #pragma unroll
        for (int r=0;r<4;r++){
            int ii = tid + 256*r;
            int jl = ii >> 3, kk = ii & 7;
            Ws[kk][jl] = (jl < OUTD) ? W2[(size_t)jl*K2TOT + kt + kk] : 0.f;
        }
        __syncthreads();
        #pragma unroll
        for (int kk=0;kk<8;kk++){
            float a[8], wv[8];
            #pragma unroll
            for (int i=0;i<8;i++) a[i]  = As[kk][mi*8+i];
            #pragma unroll
            for (int j=0;j<8;j++) wv[j] = Ws[kk][ni*8+j];
            #pragma unroll
            for (int i=0;i<8;i++)
                #pragma unroll
                for (int j=0;j<8;j++) acc[i][j] += a[i]*wv[j];
        }
    }
    #pragma unroll
    for (int i=0;i<8;i++){
        int r2 = m0 + mi*8 + i;          // r2 = t*BB + b
        int tt = r2 >> 7, bb = r2 & 127;
        size_t row = (size_t)(bb*TT + tt)*OUTD;
        #pragma unroll
        for (int j=0;j<8;j++){
            int jg = ni*8 + j;
            if (jg < OUTD) out[row + jg] = acc[i][j] + b2[jg];
        }
    }
}

// ---------------- final states -------------------------------------------------
__global__ void k_states(float* __restrict__ out, int out_size)
{
    const int base = BB*TT*OUTD;
    if (base + 4*BB*HH > out_size) return;
    int i = blockIdx.x*256 + threadIdx.x;
    if (i < BB*HH){
        out[base            + i] = g_h1f[i];
        out[base +   BB*HH  + i] = g_c1f[i];
        out[base + 2*BB*HH  + i] = g_h2f[i];
        out[base + 3*BB*HH  + i] = g_c2f[i];
    }
}

// ---------------- launch -------------------------------------------------------
extern "C" void kernel_launch(void* const* d_in, const int* in_sizes, int n_in,
                              void* d_out, int out_size)
{
    const float* x    = (const float*)d_in[0];
    const float* sent = (const float*)d_in[1];
    const float* h1h  = (const float*)d_in[2];
    const float* h1c  = (const float*)d_in[3];
    const float* h2h  = (const float*)d_in[4];
    const float* h2c  = (const float*)d_in[5];
    const float* Wihc = (const float*)d_in[6];
    const float* Whhc = (const float*)d_in[7];
    const float* bc   = (const float*)d_in[8];
    const float* Wihl = (const float*)d_in[9];
    const float* Whhl = (const float*)d_in[10];
    const float* bl   = (const float*)d_in[11];
    const float* W1   = (const float*)d_in[12];
    const float* b1   = (const float*)d_in[13];
    const float* W2   = (const float*)d_in[14];
    const float* b2   = (const float*)d_in[15];
    float* out = (float*)d_out;

    const int SMEM1 = (18432 + 8192 + 3840 + 512 + 32 + 64) * 4;   // 124288 B
    const int SMEM2 = (16384 + 8192) * 4;                          //  98304 B
    // idempotent; ignore errors (already set from the correctness run if capturing)
    cudaFuncSetAttribute(k_rec1, cudaFuncAttributeMaxDynamicSharedMemorySize, SMEM1);
    cudaFuncSetAttribute(k_rec2, cudaFuncAttributeMaxDynamicSharedMemorySize, SMEM2);

    k_init<<<256,256>>>(h1h, h2h);
    k_rec1<<<NBLK,512,SMEM1>>>(x, Wihc, Whhc, bc, W1, b1, sent, h1c);
    k_l2in<<<dim3(16,TT),256>>>(x, Wihl, bl);
    k_rec2<<<NBLK,512,SMEM2>>>(Whhl, h2c);
    k_out<<<256,256>>>(W2, b2, out);
    k_states<<<(BB*HH+255)/256,256>>>(out, out_size);
}